// round 2
// baseline (speedup 1.0000x reference)
#include <cuda_runtime.h>
#include <cuda_bf16.h>
#include <math.h>

// ---------------------------------------------------------------------------
// Problem constants
// ---------------------------------------------------------------------------
#define N_ROI   1000
#define FH      38
#define FW      50
#define FC      512
#define CROP    14
#define POOL    7
#define DFLAT   (POOL*POOL*FC)      // 25088
#define DHID    4096
#define NCLS    21
#define NREG    80

// ---------------------------------------------------------------------------
// Scratch (device globals — no allocation allowed)
// ---------------------------------------------------------------------------
__device__ float g_x0[N_ROI * DFLAT];   // pooled+flattened ROI features
__device__ float g_x1[N_ROI * DHID];    // FC1 output
__device__ float g_x2[N_ROI * DHID];    // FC2 output

// ---------------------------------------------------------------------------
// Kernel 1: crop_and_resize (TF semantics) + 2x2 maxpool, fused.
// grid = (1000, 7) : (roi, pooled_row). block = 128 threads (4 channels each).
// ---------------------------------------------------------------------------
__global__ __launch_bounds__(128)
void roi_pool_kernel(const float* __restrict__ feats,
                     const float* __restrict__ props,
                     float* __restrict__ x0)
{
    const int n  = blockIdx.x;
    const int py = blockIdx.y;
    const int c4 = threadIdx.x;          // float4 channel group: channels 4*c4..4*c4+3

    const float y1 = props[n*4 + 0];
    const float x1 = props[n*4 + 1];
    const float y2 = props[n*4 + 2];
    const float x2 = props[n*4 + 3];

    const float Hm1 = (float)(FH - 1);   // 37
    const float Wm1 = (float)(FW - 1);   // 49
    const float ystep = (y2 - y1) * Hm1 * (1.0f / (CROP - 1));
    const float xstep = (x2 - x1) * Wm1 * (1.0f / (CROP - 1));
    const float ybase = y1 * Hm1;
    const float xbase = x1 * Wm1;

    // Precompute the two sample rows for this pooled row
    int   y0i[2], y1i[2];
    float wy[2];
    #pragma unroll
    for (int dy = 0; dy < 2; dy++) {
        float ys = ybase + (float)(2*py + dy) * ystep;
        float yf = floorf(ys);
        wy[dy] = ys - yf;
        int yi = (int)yf;
        if (yi < 0) yi = 0;
        if (yi > FH-1) yi = FH-1;
        y0i[dy] = yi;
        y1i[dy] = (yi + 1 < FH-1) ? (yi + 1) : (FH-1);
    }

    for (int px = 0; px < POOL; px++) {
        float4 mx = make_float4(-1e30f, -1e30f, -1e30f, -1e30f);
        #pragma unroll
        for (int dx = 0; dx < 2; dx++) {
            float xs = xbase + (float)(2*px + dx) * xstep;
            float xf = floorf(xs);
            float wx = xs - xf;
            int xi = (int)xf;
            if (xi < 0) xi = 0;
            if (xi > FW-1) xi = FW-1;
            int x0c = xi;
            int x1c = (xi + 1 < FW-1) ? (xi + 1) : (FW-1);
            #pragma unroll
            for (int dy = 0; dy < 2; dy++) {
                const float4* r0 = (const float4*)&feats[((size_t)y0i[dy]*FW)*FC];
                const float4* r1 = (const float4*)&feats[((size_t)y1i[dy]*FW)*FC];
                float4 v00 = r0[(size_t)x0c*(FC/4) + c4];
                float4 v01 = r0[(size_t)x1c*(FC/4) + c4];
                float4 v10 = r1[(size_t)x0c*(FC/4) + c4];
                float4 v11 = r1[(size_t)x1c*(FC/4) + c4];
                float w = wy[dy];
                float4 top, bot, val;
                top.x = v00.x + (v01.x - v00.x) * wx;
                top.y = v00.y + (v01.y - v00.y) * wx;
                top.z = v00.z + (v01.z - v00.z) * wx;
                top.w = v00.w + (v01.w - v00.w) * wx;
                bot.x = v10.x + (v11.x - v10.x) * wx;
                bot.y = v10.y + (v11.y - v10.y) * wx;
                bot.z = v10.z + (v11.z - v10.z) * wx;
                bot.w = v10.w + (v11.w - v10.w) * wx;
                // Match reference exactly: top*(1-wx)+... is algebraically the lerp above;
                // use the reference's form to keep bit-level drift minimal:
                val.x = top.x + (bot.x - top.x) * w;
                val.y = top.y + (bot.y - top.y) * w;
                val.z = top.z + (bot.z - top.z) * w;
                val.w = top.w + (bot.w - top.w) * w;
                mx.x = fmaxf(mx.x, val.x);
                mx.y = fmaxf(mx.y, val.y);
                mx.z = fmaxf(mx.z, val.z);
                mx.w = fmaxf(mx.w, val.w);
            }
        }
        float4* dst = (float4*)&x0[(size_t)n*DFLAT + ((size_t)(py*POOL + px))*FC];
        dst[c4] = mx;
    }
}

// ---------------------------------------------------------------------------
// Kernel 2: tiled fp32 GEMM  C[M,N] = act(A[M,K] @ B[K,N] + bias)
// BM=BN=128, BK=16, 256 threads, 8x8 per thread.
// ---------------------------------------------------------------------------
#define BM 128
#define BN 128
#define BK 16
#define TM 8
#define TN 8

__global__ __launch_bounds__(256)
void gemm_bias_act_kernel(const float* __restrict__ A,
                          const float* __restrict__ B,
                          const float* __restrict__ bias,
                          float* __restrict__ C,
                          int M, int N, int K, int relu)
{
    __shared__ float As[BK][BM];
    __shared__ float Bs[BK][BN];

    const int tid = threadIdx.x;
    const int brow = blockIdx.y;
    const int bcol = blockIdx.x;
    const int tx = tid & 15;         // 0..15
    const int ty = tid >> 4;         // 0..15

    float acc[TM][TN];
    #pragma unroll
    for (int i = 0; i < TM; i++)
        #pragma unroll
        for (int j = 0; j < TN; j++)
            acc[i][j] = 0.0f;

    for (int k0 = 0; k0 < K; k0 += BK) {
        // Load A tile (BM x BK), 512 float4 -> 2 per thread, store transposed.
        #pragma unroll
        for (int i = 0; i < 2; i++) {
            int idx = tid + i * 256;
            int row = idx >> 2;           // 0..127
            int kc  = idx & 3;            // float4 within BK
            int gm  = brow * BM + row;
            float4 v = make_float4(0.f, 0.f, 0.f, 0.f);
            if (gm < M)
                v = *(const float4*)&A[(size_t)gm * K + k0 + kc * 4];
            As[kc*4+0][row] = v.x;
            As[kc*4+1][row] = v.y;
            As[kc*4+2][row] = v.z;
            As[kc*4+3][row] = v.w;
        }
        // Load B tile (BK x BN), 512 float4 -> 2 per thread.
        #pragma unroll
        for (int i = 0; i < 2; i++) {
            int idx = tid + i * 256;
            int row = idx >> 5;           // 0..15
            int nc  = idx & 31;
            float4 v = *(const float4*)&B[(size_t)(k0 + row) * N + bcol * BN + nc * 4];
            *(float4*)&Bs[row][nc * 4] = v;
        }
        __syncthreads();

        #pragma unroll
        for (int k = 0; k < BK; k++) {
            float a[TM], b[TN];
            #pragma unroll
            for (int i = 0; i < TM; i++) a[i] = As[k][ty * TM + i];
            #pragma unroll
            for (int j = 0; j < TN; j++) b[j] = Bs[k][tx * TN + j];
            #pragma unroll
            for (int i = 0; i < TM; i++)
                #pragma unroll
                for (int j = 0; j < TN; j++)
                    acc[i][j] = fmaf(a[i], b[j], acc[i][j]);
        }
        __syncthreads();
    }

    // Epilogue: bias + optional ReLU
    #pragma unroll
    for (int i = 0; i < TM; i++) {
        int gm = brow * BM + ty * TM + i;
        if (gm >= M) continue;
        #pragma unroll
        for (int j = 0; j < TN; j += 4) {
            int gn = bcol * BN + tx * TN + j;
            float4 v;
            v.x = acc[i][j+0] + bias[gn+0];
            v.y = acc[i][j+1] + bias[gn+1];
            v.z = acc[i][j+2] + bias[gn+2];
            v.w = acc[i][j+3] + bias[gn+3];
            if (relu) {
                v.x = fmaxf(v.x, 0.f);
                v.y = fmaxf(v.y, 0.f);
                v.z = fmaxf(v.z, 0.f);
                v.w = fmaxf(v.w, 0.f);
            }
            *(float4*)&C[(size_t)gm * N + gn] = v;
        }
    }
}

// ---------------------------------------------------------------------------
// Kernel 3: heads. One block per ROI. Stage x row (4096 f32 = 16KB) in smem,
// threads 0..20 -> cls logits, threads 32..111 -> reg outputs. Softmax at end.
// ---------------------------------------------------------------------------
__global__ __launch_bounds__(128)
void head_kernel(const float* __restrict__ X,
                 const float* __restrict__ Wc, const float* __restrict__ bc,
                 const float* __restrict__ Wr, const float* __restrict__ br,
                 float* __restrict__ out)
{
    __shared__ float xs[DHID];
    __shared__ float logits[NCLS];

    const int n = blockIdx.x;
    const int t = threadIdx.x;
    const float* x = X + (size_t)n * DHID;

    for (int i = t; i < DHID; i += 128) xs[i] = x[i];
    __syncthreads();

    if (t < NCLS) {
        float acc = bc[t];
        #pragma unroll 8
        for (int k = 0; k < DHID; k++)
            acc = fmaf(xs[k], Wc[(size_t)k * NCLS + t], acc);
        logits[t] = acc;
    } else if (t >= 32 && t < 32 + NREG) {
        int j = t - 32;
        float acc = br[j];
        #pragma unroll 8
        for (int k = 0; k < DHID; k++)
            acc = fmaf(xs[k], Wr[(size_t)k * NREG + j], acc);
        out[(size_t)N_ROI * NCLS + (size_t)n * NREG + j] = acc;
    }
    __syncthreads();

    if (t == 0) {
        float m = logits[0];
        #pragma unroll
        for (int j = 1; j < NCLS; j++) m = fmaxf(m, logits[j]);
        float s = 0.f;
        float e[NCLS];
        #pragma unroll
        for (int j = 0; j < NCLS; j++) { e[j] = expf(logits[j] - m); s += e[j]; }
        float inv = 1.0f / s;
        #pragma unroll
        for (int j = 0; j < NCLS; j++) out[(size_t)n * NCLS + j] = e[j] * inv;
    }
}

// ---------------------------------------------------------------------------
// Launch
// ---------------------------------------------------------------------------
extern "C" void kernel_launch(void* const* d_in, const int* in_sizes, int n_in,
                              void* d_out, int out_size)
{
    const float* feats = (const float*)d_in[0];
    const float* props = (const float*)d_in[1];
    const float* W1    = (const float*)d_in[2];
    const float* b1    = (const float*)d_in[3];
    const float* W2    = (const float*)d_in[4];
    const float* b2    = (const float*)d_in[5];
    const float* Wc    = (const float*)d_in[6];
    const float* bc    = (const float*)d_in[7];
    const float* Wr    = (const float*)d_in[8];
    const float* br    = (const float*)d_in[9];
    float* out = (float*)d_out;

    float *x0, *x1, *x2;
    cudaGetSymbolAddress((void**)&x0, g_x0);
    cudaGetSymbolAddress((void**)&x1, g_x1);
    cudaGetSymbolAddress((void**)&x2, g_x2);

    // 1. ROI crop_and_resize + maxpool
    roi_pool_kernel<<<dim3(N_ROI, POOL), 128>>>(feats, props, x0);

    // 2. FC1: [1000, 25088] @ [25088, 4096] + b1, ReLU
    gemm_bias_act_kernel<<<dim3(DHID / BN, (N_ROI + BM - 1) / BM), 256>>>(
        x0, W1, b1, x1, N_ROI, DHID, DFLAT, 1);

    // 3. FC2: [1000, 4096] @ [4096, 4096] + b2, ReLU
    gemm_bias_act_kernel<<<dim3(DHID / BN, (N_ROI + BM - 1) / BM), 256>>>(
        x1, W2, b2, x2, N_ROI, DHID, DHID, 1);

    // 4. Heads: cls softmax + reg
    head_kernel<<<N_ROI, 128>>>(x2, Wc, bc, Wr, br, out);
}

// round 4
// speedup vs baseline: 1.6782x; 1.6782x over previous
#include <cuda_runtime.h>
#include <cuda_bf16.h>
#include <math.h>
#include <stdint.h>

// ---------------------------------------------------------------------------
// Problem constants
// ---------------------------------------------------------------------------
#define N_ROI   1000
#define M_PAD   1024
#define FH      38
#define FW      50
#define FCH     512
#define CROP    14
#define POOL    7
#define DFLAT   25088
#define DHID    4096
#define NCLS    21
#define NREG    80

// ---------------------------------------------------------------------------
// Scratch (device globals — no allocation allowed)
// ---------------------------------------------------------------------------
__device__ float g_x0[M_PAD * DFLAT];                         // pooled ROI feats (fp32, padded)
__device__ float g_x1[M_PAD * DHID];                          // FC1 out
__device__ float g_x2[M_PAD * DHID];                          // FC2 out
__device__ __nv_bfloat16 g_w1h[(size_t)DHID * DFLAT];         // W1^T hi  [N, K]
__device__ __nv_bfloat16 g_w1l[(size_t)DHID * DFLAT];         // W1^T lo
__device__ __nv_bfloat16 g_w2h[(size_t)DHID * DHID];          // W2^T hi
__device__ __nv_bfloat16 g_w2l[(size_t)DHID * DHID];          // W2^T lo

// ---------------------------------------------------------------------------
// Small asm helpers (compute_103-safe: ldmatrix / mma.sync / cp.async only)
// ---------------------------------------------------------------------------
__device__ __forceinline__ uint32_t smem_u32(const void* p) {
    uint32_t a;
    asm("{ .reg .u64 t; cvta.to.shared.u64 t, %1; cvt.u32.u64 %0, t; }" : "=r"(a) : "l"(p));
    return a;
}

__device__ __forceinline__ void ldsm4(uint32_t r[4], uint32_t addr) {
    asm volatile("ldmatrix.sync.aligned.m8n8.x4.shared.b16 {%0,%1,%2,%3}, [%4];"
                 : "=r"(r[0]), "=r"(r[1]), "=r"(r[2]), "=r"(r[3]) : "r"(addr));
}

__device__ __forceinline__ void mma16816(float d[4], const uint32_t a[4],
                                         uint32_t b0, uint32_t b1) {
    asm volatile(
        "mma.sync.aligned.m16n8k16.row.col.f32.bf16.bf16.f32 "
        "{%0,%1,%2,%3}, {%4,%5,%6,%7}, {%8,%9}, {%0,%1,%2,%3};"
        : "+f"(d[0]), "+f"(d[1]), "+f"(d[2]), "+f"(d[3])
        : "r"(a[0]), "r"(a[1]), "r"(a[2]), "r"(a[3]), "r"(b0), "r"(b1));
}

#define CP_ASYNC16(dst, src) \
    asm volatile("cp.async.cg.shared.global [%0], [%1], 16;" :: "r"(dst), "l"(src))
#define CP_COMMIT()  asm volatile("cp.async.commit_group;" ::: "memory")
#define CP_WAIT0()   asm volatile("cp.async.wait_group 0;" ::: "memory")

__device__ __forceinline__ uint32_t pack2(__nv_bfloat16 a, __nv_bfloat16 b) {
    __nv_bfloat162 t; t.x = a; t.y = b;
    return *(uint32_t*)&t;
}

// ---------------------------------------------------------------------------
// Kernel 1: crop_and_resize (TF semantics) + 2x2 maxpool, fused.
// ---------------------------------------------------------------------------
__global__ __launch_bounds__(128)
void roi_pool_kernel(const float* __restrict__ feats,
                     const float* __restrict__ props,
                     float* __restrict__ x0)
{
    const int n  = blockIdx.x;
    const int py = blockIdx.y;
    const int c4 = threadIdx.x;

    const float y1 = props[n*4 + 0];
    const float x1 = props[n*4 + 1];
    const float y2 = props[n*4 + 2];
    const float x2 = props[n*4 + 3];

    const float Hm1 = (float)(FH - 1);
    const float Wm1 = (float)(FW - 1);
    const float ystep = (y2 - y1) * Hm1 * (1.0f / (CROP - 1));
    const float xstep = (x2 - x1) * Wm1 * (1.0f / (CROP - 1));
    const float ybase = y1 * Hm1;
    const float xbase = x1 * Wm1;

    int   y0i[2], y1i[2];
    float wy[2];
    #pragma unroll
    for (int dy = 0; dy < 2; dy++) {
        float ys = ybase + (float)(2*py + dy) * ystep;
        float yf = floorf(ys);
        wy[dy] = ys - yf;
        int yi = (int)yf;
        if (yi < 0) yi = 0;
        if (yi > FH-1) yi = FH-1;
        y0i[dy] = yi;
        y1i[dy] = (yi + 1 < FH-1) ? (yi + 1) : (FH-1);
    }

    for (int px = 0; px < POOL; px++) {
        float4 mx = make_float4(-1e30f, -1e30f, -1e30f, -1e30f);
        #pragma unroll
        for (int dx = 0; dx < 2; dx++) {
            float xs = xbase + (float)(2*px + dx) * xstep;
            float xf = floorf(xs);
            float wx = xs - xf;
            int xi = (int)xf;
            if (xi < 0) xi = 0;
            if (xi > FW-1) xi = FW-1;
            int x0c = xi;
            int x1c = (xi + 1 < FW-1) ? (xi + 1) : (FW-1);
            #pragma unroll
            for (int dy = 0; dy < 2; dy++) {
                const float4* r0 = (const float4*)&feats[((size_t)y0i[dy]*FW)*FCH];
                const float4* r1 = (const float4*)&feats[((size_t)y1i[dy]*FW)*FCH];
                float4 v00 = r0[(size_t)x0c*(FCH/4) + c4];
                float4 v01 = r0[(size_t)x1c*(FCH/4) + c4];
                float4 v10 = r1[(size_t)x0c*(FCH/4) + c4];
                float4 v11 = r1[(size_t)x1c*(FCH/4) + c4];
                float w = wy[dy];
                float4 top, bot, val;
                top.x = v00.x + (v01.x - v00.x) * wx;
                top.y = v00.y + (v01.y - v00.y) * wx;
                top.z = v00.z + (v01.z - v00.z) * wx;
                top.w = v00.w + (v01.w - v00.w) * wx;
                bot.x = v10.x + (v11.x - v10.x) * wx;
                bot.y = v10.y + (v11.y - v10.y) * wx;
                bot.z = v10.z + (v11.z - v10.z) * wx;
                bot.w = v10.w + (v11.w - v10.w) * wx;
                val.x = top.x + (bot.x - top.x) * w;
                val.y = top.y + (bot.y - top.y) * w;
                val.z = top.z + (bot.z - top.z) * w;
                val.w = top.w + (bot.w - top.w) * w;
                mx.x = fmaxf(mx.x, val.x);
                mx.y = fmaxf(mx.y, val.y);
                mx.z = fmaxf(mx.z, val.z);
                mx.w = fmaxf(mx.w, val.w);
            }
        }
        float4* dst = (float4*)&x0[(size_t)n*DFLAT + ((size_t)(py*POOL + px))*FCH];
        dst[c4] = mx;
    }
}

// ---------------------------------------------------------------------------
// Kernel 2: W [K,N] fp32 -> W^T hi/lo [N,K] bf16. Tile 64k x 32n per block.
// ---------------------------------------------------------------------------
__global__ __launch_bounds__(256)
void convert_w_kernel(const float* __restrict__ W,
                      __nv_bfloat16* __restrict__ Th,
                      __nv_bfloat16* __restrict__ Tl,
                      int K, int N)
{
    __shared__ float ts[64][33];
    const int tx = threadIdx.x & 31;
    const int ty = threadIdx.x >> 5;       // 0..7
    const int kb = blockIdx.y * 64;
    const int nb = blockIdx.x * 32;

    #pragma unroll
    for (int j = 0; j < 8; j++) {
        int r = ty + j * 8;
        ts[r][tx] = W[(size_t)(kb + r) * N + nb + tx];
    }
    __syncthreads();

    #pragma unroll
    for (int j = 0; j < 4; j++) {
        int n = ty + j * 8;
        float a = ts[2*tx][n];
        float b = ts[2*tx + 1][n];
        __nv_bfloat16 ah = __float2bfloat16_rn(a);
        __nv_bfloat16 bh = __float2bfloat16_rn(b);
        __nv_bfloat16 al = __float2bfloat16_rn(a - __bfloat162float(ah));
        __nv_bfloat16 bl = __float2bfloat16_rn(b - __bfloat162float(bh));
        size_t o = (size_t)(nb + n) * K + kb + 2 * tx;
        *(uint32_t*)&Th[o] = pack2(ah, bh);
        *(uint32_t*)&Tl[o] = pack2(al, bl);
    }
}

// ---------------------------------------------------------------------------
// Kernel 3: HMMA bf16 3-product GEMM (mma.sync.m16n8k16).
// C[1024, 4096] = relu(A_fp32 @ Bt^T + bias).
// BM=128, BN=256, BK=32, 256 threads, warp tile 64x64, 2-stage cp.async pipe.
// SMEM rows: 32 bf16 data, pitch 80B -> conflict-free ldmatrix.
// ---------------------------------------------------------------------------
#define PITCH 80
#define AH_OFF 0
#define AL_OFF 10240
#define BH_OFF 20480
#define BL_OFF 40960
#define STAGE  61440
#define GEMM_SMEM (2 * STAGE)     // 122880 B

__global__ __launch_bounds__(256, 1)
void gemm_tc_kernel(const float* __restrict__ A, int m_real,
                    const __nv_bfloat16* __restrict__ Bh,
                    const __nv_bfloat16* __restrict__ Bl,
                    const float* __restrict__ bias,
                    float* __restrict__ C, int K)
{
    extern __shared__ char smem[];
    const uint32_t sb0 = smem_u32(smem);
    const int tid  = threadIdx.x;
    const int wid  = tid >> 5;
    const int lane = tid & 31;
    const int wm   = wid & 1;            // 0..1
    const int wn   = wid >> 1;           // 0..3
    const int bn = blockIdx.x, bm = blockIdx.y;
    const int nch = K >> 5;

    const uint32_t lm_off = (uint32_t)((lane & 15) * PITCH + (lane >> 4) * 16);

    // per-thread load roles
    const int a_row  = tid >> 1;          // 0..127
    const int a_half = tid & 1;           // k 0-15 / 16-31
    const int a_gm   = bm * 128 + a_row;
    const bool a_ok  = (a_gm < m_real);
    const float* a_src_base = A + (size_t)a_gm * K + a_half * 16;
    const uint32_t a_dst_off = (uint32_t)(a_row * PITCH + a_half * 32);

    const __nv_bfloat16* bh_src_base = Bh + (size_t)(bn * 256 + tid) * K;
    const __nv_bfloat16* bl_src_base = Bl + (size_t)(bn * 256 + tid) * K;
    const uint32_t b_dst_off = (uint32_t)(tid * PITCH);

    float acc[4][8][4];
    #pragma unroll
    for (int i = 0; i < 4; i++)
        #pragma unroll
        for (int j = 0; j < 8; j++)
            #pragma unroll
            for (int e = 0; e < 4; e++) acc[i][j][e] = 0.0f;

    // ---- prologue: fill stage 0 ----
    {
        const uint32_t st = sb0;
        // B via cp.async
        #pragma unroll
        for (int c = 0; c < 4; c++) {
            CP_ASYNC16(st + BH_OFF + b_dst_off + c * 16, bh_src_base + c * 8);
            CP_ASYNC16(st + BL_OFF + b_dst_off + c * 16, bl_src_base + c * 8);
        }
        CP_COMMIT();
        // A: load, split, store
        float4 f[4];
        #pragma unroll
        for (int i = 0; i < 4; i++)
            f[i] = a_ok ? *(const float4*)(a_src_base + i * 4)
                        : make_float4(0.f, 0.f, 0.f, 0.f);
        uint32_t h[8], l[8];
        const float* v = (const float*)f;
        #pragma unroll
        for (int e = 0; e < 8; e++) {
            __nv_bfloat16 h0 = __float2bfloat16_rn(v[2*e]);
            __nv_bfloat16 h1 = __float2bfloat16_rn(v[2*e+1]);
            __nv_bfloat16 l0 = __float2bfloat16_rn(v[2*e]   - __bfloat162float(h0));
            __nv_bfloat16 l1 = __float2bfloat16_rn(v[2*e+1] - __bfloat162float(h1));
            h[e] = pack2(h0, h1);
            l[e] = pack2(l0, l1);
        }
        *(uint4*)(smem + AH_OFF + a_dst_off)      = make_uint4(h[0],h[1],h[2],h[3]);
        *(uint4*)(smem + AH_OFF + a_dst_off + 16) = make_uint4(h[4],h[5],h[6],h[7]);
        *(uint4*)(smem + AL_OFF + a_dst_off)      = make_uint4(l[0],l[1],l[2],l[3]);
        *(uint4*)(smem + AL_OFF + a_dst_off + 16) = make_uint4(l[4],l[5],l[6],l[7]);
    }

    for (int c = 0; c < nch; c++) {
        const int s = c & 1;
        const uint32_t st  = sb0 + (uint32_t)s * STAGE;
        const char* stp    = smem + (size_t)s * STAGE;
        const uint32_t stn = sb0 + (uint32_t)(s ^ 1) * STAGE;
        char* stnp         = smem + (size_t)(s ^ 1) * STAGE;

        CP_WAIT0();
        __syncthreads();

        const bool has_next = (c + 1 < nch);
        float4 f[4];
        if (has_next) {
            const int k1 = (c + 1) << 5;
            // B for next stage
            #pragma unroll
            for (int cc = 0; cc < 4; cc++) {
                CP_ASYNC16(stn + BH_OFF + b_dst_off + cc * 16, bh_src_base + k1 + cc * 8);
                CP_ASYNC16(stn + BL_OFF + b_dst_off + cc * 16, bl_src_base + k1 + cc * 8);
            }
            CP_COMMIT();
            // A for next stage -> regs
            #pragma unroll
            for (int i = 0; i < 4; i++)
                f[i] = a_ok ? *(const float4*)(a_src_base + k1 + i * 4)
                            : make_float4(0.f, 0.f, 0.f, 0.f);
        }

        // ---- compute stage s ----
        #pragma unroll
        for (int kk = 0; kk < 2; kk++) {
            uint32_t ah[4][4], al[4][4];
            #pragma unroll
            for (int mt = 0; mt < 4; mt++) {
                uint32_t ra = st + AH_OFF + (uint32_t)((wm*64 + mt*16) * PITCH + kk*32) + lm_off;
                ldsm4(ah[mt], ra);
                ldsm4(al[mt], ra + (AL_OFF - AH_OFF));
            }
            #pragma unroll
            for (int nt2 = 0; nt2 < 4; nt2++) {
                uint32_t rb = st + BH_OFF + (uint32_t)((wn*64 + nt2*16) * PITCH + kk*32) + lm_off;
                uint32_t qh[4], ql[4];
                ldsm4(qh, rb);
                ldsm4(ql, rb + (BL_OFF - BH_OFF));
                #pragma unroll
                for (int mt = 0; mt < 4; mt++) {
                    mma16816(acc[mt][2*nt2],   ah[mt], qh[0], qh[2]);
                    mma16816(acc[mt][2*nt2+1], ah[mt], qh[1], qh[3]);
                    mma16816(acc[mt][2*nt2],   al[mt], qh[0], qh[2]);
                    mma16816(acc[mt][2*nt2+1], al[mt], qh[1], qh[3]);
                    mma16816(acc[mt][2*nt2],   ah[mt], ql[0], ql[2]);
                    mma16816(acc[mt][2*nt2+1], ah[mt], ql[1], ql[3]);
                }
            }
        }

        if (has_next) {
            uint32_t h[8], l[8];
            const float* v = (const float*)f;
            #pragma unroll
            for (int e = 0; e < 8; e++) {
                __nv_bfloat16 h0 = __float2bfloat16_rn(v[2*e]);
                __nv_bfloat16 h1 = __float2bfloat16_rn(v[2*e+1]);
                __nv_bfloat16 l0 = __float2bfloat16_rn(v[2*e]   - __bfloat162float(h0));
                __nv_bfloat16 l1 = __float2bfloat16_rn(v[2*e+1] - __bfloat162float(h1));
                h[e] = pack2(h0, h1);
                l[e] = pack2(l0, l1);
            }
            *(uint4*)(stnp + AH_OFF + a_dst_off)      = make_uint4(h[0],h[1],h[2],h[3]);
            *(uint4*)(stnp + AH_OFF + a_dst_off + 16) = make_uint4(h[4],h[5],h[6],h[7]);
            *(uint4*)(stnp + AL_OFF + a_dst_off)      = make_uint4(l[0],l[1],l[2],l[3]);
            *(uint4*)(stnp + AL_OFF + a_dst_off + 16) = make_uint4(l[4],l[5],l[6],l[7]);
        }
        (void)stp;
    }

    // ---- epilogue: bias + relu, write fp32 ----
    #pragma unroll
    for (int mt = 0; mt < 4; mt++) {
        const int row0 = bm*128 + wm*64 + mt*16 + (lane >> 2);
        #pragma unroll
        for (int nt = 0; nt < 8; nt++) {
            const int gn = bn*256 + wn*64 + nt*8 + 2*(lane & 3);
            float b0 = bias[gn], b1 = bias[gn+1];
            float2 v0, v1;
            v0.x = fmaxf(acc[mt][nt][0] + b0, 0.f);
            v0.y = fmaxf(acc[mt][nt][1] + b1, 0.f);
            v1.x = fmaxf(acc[mt][nt][2] + b0, 0.f);
            v1.y = fmaxf(acc[mt][nt][3] + b1, 0.f);
            *(float2*)&C[(size_t)row0 * DHID + gn]       = v0;
            *(float2*)&C[(size_t)(row0+8) * DHID + gn]   = v1;
        }
    }
}

// ---------------------------------------------------------------------------
// Kernel 4: heads, 8 ROIs per block.
// ---------------------------------------------------------------------------
#define HEAD_SMEM (8 * DHID * 4 + 8 * 32 * 4)

__global__ __launch_bounds__(128)
void head_kernel(const float* __restrict__ X,
                 const float* __restrict__ Wc, const float* __restrict__ bc,
                 const float* __restrict__ Wr, const float* __restrict__ br,
                 float* __restrict__ out)
{
    extern __shared__ float xs[];             // [4096][8]
    float* logits = xs + 8 * DHID;            // [8][32]
    const int b = blockIdx.x, t = threadIdx.x;

    for (int idx = t; idx < 8 * DHID; idx += 128) {
        int r = idx >> 12, k = idx & (DHID - 1);
        xs[k * 8 + r] = X[(size_t)(b * 8 + r) * DHID + k];
    }
    __syncthreads();

    if (t < NCLS + NREG) {
        const bool is_cls = (t < NCLS);
        const float* W = is_cls ? Wc : Wr;
        const int nc   = is_cls ? NCLS : NREG;
        const int j    = is_cls ? t : (t - NCLS);
        const float bv = is_cls ? bc[j] : br[j];
        float acc[8];
        #pragma unroll
        for (int r = 0; r < 8; r++) acc[r] = bv;
        #pragma unroll 4
        for (int k = 0; k < DHID; k++) {
            float w = W[(size_t)k * nc + j];
            float4 a = *(float4*)&xs[k * 8];
            float4 bq = *(float4*)&xs[k * 8 + 4];
            acc[0] = fmaf(a.x,  w, acc[0]);
            acc[1] = fmaf(a.y,  w, acc[1]);
            acc[2] = fmaf(a.z,  w, acc[2]);
            acc[3] = fmaf(a.w,  w, acc[3]);
            acc[4] = fmaf(bq.x, w, acc[4]);
            acc[5] = fmaf(bq.y, w, acc[5]);
            acc[6] = fmaf(bq.z, w, acc[6]);
            acc[7] = fmaf(bq.w, w, acc[7]);
        }
        if (is_cls) {
            #pragma unroll
            for (int r = 0; r < 8; r++) logits[r * 32 + j] = acc[r];
        } else {
            #pragma unroll
            for (int r = 0; r < 8; r++)
                out[(size_t)N_ROI * NCLS + (size_t)(b * 8 + r) * NREG + j] = acc[r];
        }
    }
    __syncthreads();

    if (t < 8) {
        int roi = b * 8 + t;
        float m = logits[t * 32];
        #pragma unroll
        for (int j = 1; j < NCLS; j++) m = fmaxf(m, logits[t * 32 + j]);
        float e[NCLS], s = 0.f;
        #pragma unroll
        for (int j = 0; j < NCLS; j++) { e[j] = expf(logits[t * 32 + j] - m); s += e[j]; }
        float inv = 1.0f / s;
        #pragma unroll
        for (int j = 0; j < NCLS; j++) out[(size_t)roi * NCLS + j] = e[j] * inv;
    }
}

// ---------------------------------------------------------------------------
// Launch
// ---------------------------------------------------------------------------
extern "C" void kernel_launch(void* const* d_in, const int* in_sizes, int n_in,
                              void* d_out, int out_size)
{
    const float* feats = (const float*)d_in[0];
    const float* props = (const float*)d_in[1];
    const float* W1    = (const float*)d_in[2];
    const float* b1    = (const float*)d_in[3];
    const float* W2    = (const float*)d_in[4];
    const float* b2    = (const float*)d_in[5];
    const float* Wc    = (const float*)d_in[6];
    const float* bc    = (const float*)d_in[7];
    const float* Wr    = (const float*)d_in[8];
    const float* br    = (const float*)d_in[9];
    float* out = (float*)d_out;

    float *x0, *x1, *x2;
    __nv_bfloat16 *w1h, *w1l, *w2h, *w2l;
    cudaGetSymbolAddress((void**)&x0,  g_x0);
    cudaGetSymbolAddress((void**)&x1,  g_x1);
    cudaGetSymbolAddress((void**)&x2,  g_x2);
    cudaGetSymbolAddress((void**)&w1h, g_w1h);
    cudaGetSymbolAddress((void**)&w1l, g_w1l);
    cudaGetSymbolAddress((void**)&w2h, g_w2h);
    cudaGetSymbolAddress((void**)&w2l, g_w2l);

    cudaFuncSetAttribute(gemm_tc_kernel, cudaFuncAttributeMaxDynamicSharedMemorySize, GEMM_SMEM);
    cudaFuncSetAttribute(head_kernel,    cudaFuncAttributeMaxDynamicSharedMemorySize, HEAD_SMEM);

    // 1. ROI crop_and_resize + maxpool -> x0 fp32
    roi_pool_kernel<<<dim3(N_ROI, POOL), 128>>>(feats, props, x0);

    // 2. Weight convert+transpose -> bf16 hi/lo K-major
    convert_w_kernel<<<dim3(DHID / 32, DFLAT / 64), 256>>>(W1, w1h, w1l, DFLAT, DHID);
    convert_w_kernel<<<dim3(DHID / 32, DHID  / 64), 256>>>(W2, w2h, w2l, DHID,  DHID);

    // 3. FC1: [1024(1000), 25088] @ W1 -> relu -> x1
    gemm_tc_kernel<<<dim3(DHID / 256, M_PAD / 128), 256, GEMM_SMEM>>>(
        x0, N_ROI, w1h, w1l, b1, x1, DFLAT);

    // 4. FC2: [1024, 4096] @ W2 -> relu -> x2
    gemm_tc_kernel<<<dim3(DHID / 256, M_PAD / 128), 256, GEMM_SMEM>>>(
        x1, M_PAD, w2h, w2l, b2, x2, DHID);

    // 5. Heads
    head_kernel<<<N_ROI / 8, 128, HEAD_SMEM>>>(x2, Wc, bc, Wr, br, out);
}

// round 5
// speedup vs baseline: 1.8762x; 1.1180x over previous
#include <cuda_runtime.h>
#include <cuda_bf16.h>
#include <math.h>
#include <stdint.h>

// ---------------------------------------------------------------------------
// Problem constants
// ---------------------------------------------------------------------------
#define N_ROI   1000
#define M_PAD   1024
#define FH      38
#define FW      50
#define FCH     512
#define CROP    14
#define POOL    7
#define DFLAT   25088
#define DHID    4096
#define NCLS    21
#define NREG    80

// ---------------------------------------------------------------------------
// Scratch (device globals — no allocation allowed)
// ---------------------------------------------------------------------------
__device__ __nv_bfloat16 g_x0h[(size_t)M_PAD * DFLAT];
__device__ __nv_bfloat16 g_x0l[(size_t)M_PAD * DFLAT];
__device__ __nv_bfloat16 g_x1h[(size_t)M_PAD * DHID];
__device__ __nv_bfloat16 g_x1l[(size_t)M_PAD * DHID];
__device__ float         g_x2 [(size_t)M_PAD * DHID];
__device__ __nv_bfloat16 g_w1h[(size_t)DHID * DFLAT];
__device__ __nv_bfloat16 g_w1l[(size_t)DHID * DFLAT];
__device__ __nv_bfloat16 g_w2h[(size_t)DHID * DHID];
__device__ __nv_bfloat16 g_w2l[(size_t)DHID * DHID];

// ---------------------------------------------------------------------------
// asm helpers (compute_103-safe)
// ---------------------------------------------------------------------------
__device__ __forceinline__ uint32_t smem_u32(const void* p) {
    uint32_t a;
    asm("{ .reg .u64 t; cvta.to.shared.u64 t, %1; cvt.u32.u64 %0, t; }" : "=r"(a) : "l"(p));
    return a;
}
__device__ __forceinline__ void ldsm4(uint32_t r[4], uint32_t addr) {
    asm volatile("ldmatrix.sync.aligned.m8n8.x4.shared.b16 {%0,%1,%2,%3}, [%4];"
                 : "=r"(r[0]), "=r"(r[1]), "=r"(r[2]), "=r"(r[3]) : "r"(addr));
}
__device__ __forceinline__ void mma16816(float d[4], const uint32_t a[4],
                                         uint32_t b0, uint32_t b1) {
    asm volatile(
        "mma.sync.aligned.m16n8k16.row.col.f32.bf16.bf16.f32 "
        "{%0,%1,%2,%3}, {%4,%5,%6,%7}, {%8,%9}, {%0,%1,%2,%3};"
        : "+f"(d[0]), "+f"(d[1]), "+f"(d[2]), "+f"(d[3])
        : "r"(a[0]), "r"(a[1]), "r"(a[2]), "r"(a[3]), "r"(b0), "r"(b1));
}
#define CP_A16(dst, src) \
    asm volatile("cp.async.cg.shared.global [%0], [%1], 16;" :: "r"(dst), "l"(src))
#define CP_A16Z(dst, src, n) \
    asm volatile("cp.async.cg.shared.global [%0], [%1], 16, %2;" :: "r"(dst), "l"(src), "r"(n))
#define CP_COMMIT()      asm volatile("cp.async.commit_group;" ::: "memory")
#define CP_WAIT_GROUP(n) asm volatile("cp.async.wait_group %0;" :: "n"(n) : "memory")

__device__ __forceinline__ uint32_t pack2(__nv_bfloat16 a, __nv_bfloat16 b) {
    __nv_bfloat162 t; t.x = a; t.y = b;
    return *(uint32_t*)&t;
}

// ---------------------------------------------------------------------------
// Kernel 1: crop_and_resize + 2x2 maxpool, emits bf16 hi/lo split directly.
// ---------------------------------------------------------------------------
__global__ __launch_bounds__(128)
void roi_pool_kernel(const float* __restrict__ feats,
                     const float* __restrict__ props,
                     __nv_bfloat16* __restrict__ x0h,
                     __nv_bfloat16* __restrict__ x0l)
{
    const int n  = blockIdx.x;
    const int py = blockIdx.y;
    const int c4 = threadIdx.x;

    const float y1 = props[n*4 + 0];
    const float x1 = props[n*4 + 1];
    const float y2 = props[n*4 + 2];
    const float x2 = props[n*4 + 3];

    const float Hm1 = (float)(FH - 1);
    const float Wm1 = (float)(FW - 1);
    const float ystep = (y2 - y1) * Hm1 * (1.0f / (CROP - 1));
    const float xstep = (x2 - x1) * Wm1 * (1.0f / (CROP - 1));
    const float ybase = y1 * Hm1;
    const float xbase = x1 * Wm1;

    int   y0i[2], y1i[2];
    float wy[2];
    #pragma unroll
    for (int dy = 0; dy < 2; dy++) {
        float ys = ybase + (float)(2*py + dy) * ystep;
        float yf = floorf(ys);
        wy[dy] = ys - yf;
        int yi = (int)yf;
        if (yi < 0) yi = 0;
        if (yi > FH-1) yi = FH-1;
        y0i[dy] = yi;
        y1i[dy] = (yi + 1 < FH-1) ? (yi + 1) : (FH-1);
    }

    for (int px = 0; px < POOL; px++) {
        float4 mx = make_float4(-1e30f, -1e30f, -1e30f, -1e30f);
        #pragma unroll
        for (int dx = 0; dx < 2; dx++) {
            float xs = xbase + (float)(2*px + dx) * xstep;
            float xf = floorf(xs);
            float wx = xs - xf;
            int xi = (int)xf;
            if (xi < 0) xi = 0;
            if (xi > FW-1) xi = FW-1;
            int x0c = xi;
            int x1c = (xi + 1 < FW-1) ? (xi + 1) : (FW-1);
            #pragma unroll
            for (int dy = 0; dy < 2; dy++) {
                const float4* r0 = (const float4*)&feats[((size_t)y0i[dy]*FW)*FCH];
                const float4* r1 = (const float4*)&feats[((size_t)y1i[dy]*FW)*FCH];
                float4 v00 = r0[(size_t)x0c*(FCH/4) + c4];
                float4 v01 = r0[(size_t)x1c*(FCH/4) + c4];
                float4 v10 = r1[(size_t)x0c*(FCH/4) + c4];
                float4 v11 = r1[(size_t)x1c*(FCH/4) + c4];
                float w = wy[dy];
                float4 top, bot, val;
                top.x = v00.x + (v01.x - v00.x) * wx;
                top.y = v00.y + (v01.y - v00.y) * wx;
                top.z = v00.z + (v01.z - v00.z) * wx;
                top.w = v00.w + (v01.w - v00.w) * wx;
                bot.x = v10.x + (v11.x - v10.x) * wx;
                bot.y = v10.y + (v11.y - v10.y) * wx;
                bot.z = v10.z + (v11.z - v10.z) * wx;
                bot.w = v10.w + (v11.w - v10.w) * wx;
                val.x = top.x + (bot.x - top.x) * w;
                val.y = top.y + (bot.y - top.y) * w;
                val.z = top.z + (bot.z - top.z) * w;
                val.w = top.w + (bot.w - top.w) * w;
                mx.x = fmaxf(mx.x, val.x);
                mx.y = fmaxf(mx.y, val.y);
                mx.z = fmaxf(mx.z, val.z);
                mx.w = fmaxf(mx.w, val.w);
            }
        }
        // split to bf16 hi/lo
        const float* v = (const float*)&mx;
        __nv_bfloat16 h[4], l[4];
        #pragma unroll
        for (int e = 0; e < 4; e++) {
            h[e] = __float2bfloat16_rn(v[e]);
            l[e] = __float2bfloat16_rn(v[e] - __bfloat162float(h[e]));
        }
        size_t idx = (size_t)n*DFLAT + ((size_t)(py*POOL + px))*FCH + (size_t)c4*4;
        *(uint2*)&x0h[idx] = make_uint2(pack2(h[0],h[1]), pack2(h[2],h[3]));
        *(uint2*)&x0l[idx] = make_uint2(pack2(l[0],l[1]), pack2(l[2],l[3]));
    }
}

// ---------------------------------------------------------------------------
// Kernel 2: W [K,N] fp32 -> W^T hi/lo [N,K] bf16.
// ---------------------------------------------------------------------------
__global__ __launch_bounds__(256)
void convert_w_kernel(const float* __restrict__ W,
                      __nv_bfloat16* __restrict__ Th,
                      __nv_bfloat16* __restrict__ Tl,
                      int K, int N)
{
    __shared__ float ts[64][33];
    const int tx = threadIdx.x & 31;
    const int ty = threadIdx.x >> 5;
    const int kb = blockIdx.y * 64;
    const int nb = blockIdx.x * 32;

    #pragma unroll
    for (int j = 0; j < 8; j++) {
        int r = ty + j * 8;
        ts[r][tx] = W[(size_t)(kb + r) * N + nb + tx];
    }
    __syncthreads();

    #pragma unroll
    for (int j = 0; j < 4; j++) {
        int n = ty + j * 8;
        float a = ts[2*tx][n];
        float b = ts[2*tx + 1][n];
        __nv_bfloat16 ah = __float2bfloat16_rn(a);
        __nv_bfloat16 bh = __float2bfloat16_rn(b);
        __nv_bfloat16 al = __float2bfloat16_rn(a - __bfloat162float(ah));
        __nv_bfloat16 bl = __float2bfloat16_rn(b - __bfloat162float(bh));
        size_t o = (size_t)(nb + n) * K + kb + 2 * tx;
        *(uint32_t*)&Th[o] = pack2(ah, bh);
        *(uint32_t*)&Tl[o] = pack2(al, bl);
    }
}

// ---------------------------------------------------------------------------
// Kernel 3: HMMA bf16 3-product GEMM, pre-split operands.
// C[1024, 4096] = relu(A @ B^T + bias); A = Ah+Al, B = Bh+Bl (bf16, K-major).
// BM=256, BN=128, BK=32, 512 threads, warp tile 64x32, 3-stage cp.async.
// ---------------------------------------------------------------------------
#define PITCH  80
#define AH_OFF 0
#define AL_OFF 20480
#define BH_OFF 40960
#define BL_OFF 51200
#define STAGE  61440
#define NSTAGE 3
#define GEMM_SMEM (NSTAGE * STAGE)    // 184320 B

__global__ __launch_bounds__(512, 1)
void gemm_tc_kernel(const __nv_bfloat16* __restrict__ Ah,
                    const __nv_bfloat16* __restrict__ Al,
                    int m_real,
                    const __nv_bfloat16* __restrict__ Bh,
                    const __nv_bfloat16* __restrict__ Bl,
                    const float* __restrict__ bias,
                    float* __restrict__ Cf,
                    __nv_bfloat16* __restrict__ Ch,
                    __nv_bfloat16* __restrict__ Cl,
                    int K, int out_bf16)
{
    extern __shared__ char smem[];
    const uint32_t sb0 = smem_u32(smem);
    const int tid  = threadIdx.x;
    const int wid  = tid >> 5;
    const int lane = tid & 31;
    const int wm   = wid & 3;            // 0..3 (M groups of 64)
    const int wn   = wid >> 2;           // 0..3 (N groups of 32)
    const int bn = blockIdx.x, bm = blockIdx.y;
    const int nch = K >> 5;

    const uint32_t lm_off = (uint32_t)((lane & 15) * PITCH + (lane >> 4) * 16);

    // ---- load roles ----
    // A: thread -> (row, khalf); 2 x 16B per matrix
    const int a_row  = tid >> 1;              // 0..255
    const int a_half = tid & 1;
    const int a_gm   = bm * 256 + a_row;
    const uint32_t a_fill = (a_gm < m_real) ? 16u : 0u;
    const int a_sr   = (a_gm < m_real) ? a_gm : (m_real - 1);
    const __nv_bfloat16* ah_src = Ah + (size_t)a_sr * K + a_half * 16;
    const __nv_bfloat16* al_src = Al + (size_t)a_sr * K + a_half * 16;
    const uint32_t a_dst = (uint32_t)(a_row * PITCH + a_half * 32);
    // B: thread -> (row, chunk); 1 x 16B per matrix
    const int b_row = tid >> 2;               // 0..127
    const int b_ch  = tid & 3;
    const __nv_bfloat16* bh_src = Bh + (size_t)(bn * 128 + b_row) * K + b_ch * 8;
    const __nv_bfloat16* bl_src = Bl + (size_t)(bn * 128 + b_row) * K + b_ch * 8;
    const uint32_t b_dst = (uint32_t)(b_row * PITCH + b_ch * 16);

    float acc[4][4][4];
    #pragma unroll
    for (int i = 0; i < 4; i++)
        #pragma unroll
        for (int j = 0; j < 4; j++)
            #pragma unroll
            for (int e = 0; e < 4; e++) acc[i][j][e] = 0.0f;

    // ---- prologue: stages 0,1 ----
    #pragma unroll
    for (int s = 0; s < 2; s++) {
        const uint32_t st = sb0 + (uint32_t)s * STAGE;
        const int k0 = s * 32;
        CP_A16Z(st + AH_OFF + a_dst,      ah_src + k0,     a_fill);
        CP_A16Z(st + AH_OFF + a_dst + 16, ah_src + k0 + 8, a_fill);
        CP_A16Z(st + AL_OFF + a_dst,      al_src + k0,     a_fill);
        CP_A16Z(st + AL_OFF + a_dst + 16, al_src + k0 + 8, a_fill);
        CP_A16(st + BH_OFF + b_dst, bh_src + k0);
        CP_A16(st + BL_OFF + b_dst, bl_src + k0);
        CP_COMMIT();
    }

    for (int c = 0; c < nch; c++) {
        const uint32_t st = sb0 + (uint32_t)(c % NSTAGE) * STAGE;
        CP_WAIT_GROUP(1);
        __syncthreads();

        if (c + 2 < nch) {
            const uint32_t sn = sb0 + (uint32_t)((c + 2) % NSTAGE) * STAGE;
            const int k0 = (c + 2) * 32;
            CP_A16Z(sn + AH_OFF + a_dst,      ah_src + k0,     a_fill);
            CP_A16Z(sn + AH_OFF + a_dst + 16, ah_src + k0 + 8, a_fill);
            CP_A16Z(sn + AL_OFF + a_dst,      al_src + k0,     a_fill);
            CP_A16Z(sn + AL_OFF + a_dst + 16, al_src + k0 + 8, a_fill);
            CP_A16(sn + BH_OFF + b_dst, bh_src + k0);
            CP_A16(sn + BL_OFF + b_dst, bl_src + k0);
            CP_COMMIT();
        }

        #pragma unroll
        for (int kk = 0; kk < 2; kk++) {
            uint32_t qh[2][4], ql[2][4];
            #pragma unroll
            for (int nt2 = 0; nt2 < 2; nt2++) {
                uint32_t rb = st + BH_OFF +
                    (uint32_t)((wn*32 + nt2*16) * PITCH + kk*32) + lm_off;
                ldsm4(qh[nt2], rb);
                ldsm4(ql[nt2], rb + (BL_OFF - BH_OFF));
            }
            #pragma unroll
            for (int mt = 0; mt < 4; mt++) {
                uint32_t ra = st + AH_OFF +
                    (uint32_t)((wm*64 + mt*16) * PITCH + kk*32) + lm_off;
                uint32_t ah4[4], al4[4];
                ldsm4(ah4, ra);
                ldsm4(al4, ra + (AL_OFF - AH_OFF));
                #pragma unroll
                for (int nt2 = 0; nt2 < 2; nt2++) {
                    mma16816(acc[mt][2*nt2],   ah4, qh[nt2][0], qh[nt2][2]);
                    mma16816(acc[mt][2*nt2+1], ah4, qh[nt2][1], qh[nt2][3]);
                    mma16816(acc[mt][2*nt2],   al4, qh[nt2][0], qh[nt2][2]);
                    mma16816(acc[mt][2*nt2+1], al4, qh[nt2][1], qh[nt2][3]);
                    mma16816(acc[mt][2*nt2],   ah4, ql[nt2][0], ql[nt2][2]);
                    mma16816(acc[mt][2*nt2+1], ah4, ql[nt2][1], ql[nt2][3]);
                }
            }
        }
    }

    // ---- epilogue: bias + relu ----
    #pragma unroll
    for (int mt = 0; mt < 4; mt++) {
        const int row0 = bm*256 + wm*64 + mt*16 + (lane >> 2);
        #pragma unroll
        for (int nt = 0; nt < 4; nt++) {
            const int gn = bn*128 + wn*32 + nt*8 + 2*(lane & 3);
            const float b0 = bias[gn], b1 = bias[gn+1];
            float v00 = fmaxf(acc[mt][nt][0] + b0, 0.f);
            float v01 = fmaxf(acc[mt][nt][1] + b1, 0.f);
            float v10 = fmaxf(acc[mt][nt][2] + b0, 0.f);
            float v11 = fmaxf(acc[mt][nt][3] + b1, 0.f);
            if (out_bf16) {
                __nv_bfloat16 h00 = __float2bfloat16_rn(v00);
                __nv_bfloat16 h01 = __float2bfloat16_rn(v01);
                __nv_bfloat16 h10 = __float2bfloat16_rn(v10);
                __nv_bfloat16 h11 = __float2bfloat16_rn(v11);
                __nv_bfloat16 l00 = __float2bfloat16_rn(v00 - __bfloat162float(h00));
                __nv_bfloat16 l01 = __float2bfloat16_rn(v01 - __bfloat162float(h01));
                __nv_bfloat16 l10 = __float2bfloat16_rn(v10 - __bfloat162float(h10));
                __nv_bfloat16 l11 = __float2bfloat16_rn(v11 - __bfloat162float(h11));
                *(uint32_t*)&Ch[(size_t)row0 * DHID + gn]     = pack2(h00, h01);
                *(uint32_t*)&Cl[(size_t)row0 * DHID + gn]     = pack2(l00, l01);
                *(uint32_t*)&Ch[(size_t)(row0+8) * DHID + gn] = pack2(h10, h11);
                *(uint32_t*)&Cl[(size_t)(row0+8) * DHID + gn] = pack2(l10, l11);
            } else {
                *(float2*)&Cf[(size_t)row0 * DHID + gn]     = make_float2(v00, v01);
                *(float2*)&Cf[(size_t)(row0+8) * DHID + gn] = make_float2(v10, v11);
            }
        }
    }
}

// ---------------------------------------------------------------------------
// Kernel 4: heads, 8 ROIs per block.
// ---------------------------------------------------------------------------
#define HEAD_SMEM (8 * DHID * 4 + 8 * 32 * 4)

__global__ __launch_bounds__(128)
void head_kernel(const float* __restrict__ X,
                 const float* __restrict__ Wc, const float* __restrict__ bc,
                 const float* __restrict__ Wr, const float* __restrict__ br,
                 float* __restrict__ out)
{
    extern __shared__ float xs[];             // [4096][8]
    float* logits = xs + 8 * DHID;            // [8][32]
    const int b = blockIdx.x, t = threadIdx.x;

    for (int idx = t; idx < 8 * DHID; idx += 128) {
        int r = idx >> 12, k = idx & (DHID - 1);
        xs[k * 8 + r] = X[(size_t)(b * 8 + r) * DHID + k];
    }
    __syncthreads();

    if (t < NCLS + NREG) {
        const bool is_cls = (t < NCLS);
        const float* W = is_cls ? Wc : Wr;
        const int nc   = is_cls ? NCLS : NREG;
        const int j    = is_cls ? t : (t - NCLS);
        const float bv = is_cls ? bc[j] : br[j];
        float acc[8];
        #pragma unroll
        for (int r = 0; r < 8; r++) acc[r] = bv;
        #pragma unroll 4
        for (int k = 0; k < DHID; k++) {
            float w = W[(size_t)k * nc + j];
            float4 a = *(float4*)&xs[k * 8];
            float4 bq = *(float4*)&xs[k * 8 + 4];
            acc[0] = fmaf(a.x,  w, acc[0]);
            acc[1] = fmaf(a.y,  w, acc[1]);
            acc[2] = fmaf(a.z,  w, acc[2]);
            acc[3] = fmaf(a.w,  w, acc[3]);
            acc[4] = fmaf(bq.x, w, acc[4]);
            acc[5] = fmaf(bq.y, w, acc[5]);
            acc[6] = fmaf(bq.z, w, acc[6]);
            acc[7] = fmaf(bq.w, w, acc[7]);
        }
        if (is_cls) {
            #pragma unroll
            for (int r = 0; r < 8; r++) logits[r * 32 + j] = acc[r];
        } else {
            #pragma unroll
            for (int r = 0; r < 8; r++)
                out[(size_t)N_ROI * NCLS + (size_t)(b * 8 + r) * NREG + j] = acc[r];
        }
    }
    __syncthreads();

    if (t < 8) {
        int roi = b * 8 + t;
        float m = logits[t * 32];
        #pragma unroll
        for (int j = 1; j < NCLS; j++) m = fmaxf(m, logits[t * 32 + j]);
        float e[NCLS], s = 0.f;
        #pragma unroll
        for (int j = 0; j < NCLS; j++) { e[j] = expf(logits[t * 32 + j] - m); s += e[j]; }
        float inv = 1.0f / s;
        #pragma unroll
        for (int j = 0; j < NCLS; j++) out[(size_t)roi * NCLS + j] = e[j] * inv;
    }
}

// ---------------------------------------------------------------------------
// Launch
// ---------------------------------------------------------------------------
extern "C" void kernel_launch(void* const* d_in, const int* in_sizes, int n_in,
                              void* d_out, int out_size)
{
    const float* feats = (const float*)d_in[0];
    const float* props = (const float*)d_in[1];
    const float* W1    = (const float*)d_in[2];
    const float* b1    = (const float*)d_in[3];
    const float* W2    = (const float*)d_in[4];
    const float* b2    = (const float*)d_in[5];
    const float* Wc    = (const float*)d_in[6];
    const float* bc    = (const float*)d_in[7];
    const float* Wr    = (const float*)d_in[8];
    const float* br    = (const float*)d_in[9];
    float* out = (float*)d_out;

    __nv_bfloat16 *x0h, *x0l, *x1h, *x1l, *w1h, *w1l, *w2h, *w2l;
    float *x2;
    cudaGetSymbolAddress((void**)&x0h, g_x0h);
    cudaGetSymbolAddress((void**)&x0l, g_x0l);
    cudaGetSymbolAddress((void**)&x1h, g_x1h);
    cudaGetSymbolAddress((void**)&x1l, g_x1l);
    cudaGetSymbolAddress((void**)&x2,  g_x2);
    cudaGetSymbolAddress((void**)&w1h, g_w1h);
    cudaGetSymbolAddress((void**)&w1l, g_w1l);
    cudaGetSymbolAddress((void**)&w2h, g_w2h);
    cudaGetSymbolAddress((void**)&w2l, g_w2l);

    cudaFuncSetAttribute(gemm_tc_kernel, cudaFuncAttributeMaxDynamicSharedMemorySize, GEMM_SMEM);
    cudaFuncSetAttribute(head_kernel,    cudaFuncAttributeMaxDynamicSharedMemorySize, HEAD_SMEM);

    // 1. ROI crop_and_resize + maxpool -> x0 bf16 hi/lo
    roi_pool_kernel<<<dim3(N_ROI, POOL), 128>>>(feats, props, x0h, x0l);

    // 2. Weight convert+transpose -> bf16 hi/lo K-major
    convert_w_kernel<<<dim3(DHID / 32, DFLAT / 64), 256>>>(W1, w1h, w1l, DFLAT, DHID);
    convert_w_kernel<<<dim3(DHID / 32, DHID  / 64), 256>>>(W2, w2h, w2l, DHID,  DHID);

    // 3. FC1 -> x1 bf16 hi/lo
    gemm_tc_kernel<<<dim3(DHID / 128, M_PAD / 256), 512, GEMM_SMEM>>>(
        x0h, x0l, N_ROI, w1h, w1l, b1, nullptr, x1h, x1l, DFLAT, 1);

    // 4. FC2 -> x2 fp32
    gemm_tc_kernel<<<dim3(DHID / 128, M_PAD / 256), 512, GEMM_SMEM>>>(
        x1h, x1l, M_PAD, w2h, w2l, b2, x2, nullptr, nullptr, DHID, 0);

    // 5. Heads
    head_kernel<<<N_ROI / 8, 128, HEAD_SMEM>>>(x2, Wc, bc, Wr, br, out);
}